// round 3
// baseline (speedup 1.0000x reference)
#include <cuda_runtime.h>

#define Bq 128
#define Sq 512
#define Dq 256
#define Lq 3
#define Hq 8
#define ADq 64
#define HDq 32
#define Nq (Bq*Sq)   // 65536

// ---------------- scratch (device globals; no allocation) ----------------
__device__ float g_mean[Bq*Lq*Dq];
__device__ float g_scalew[Bq*Lq];
__device__ float g_fused[16777216];  // N*D
__device__ float g_q[16777216];
__device__ float g_k[16777216];
__device__ float g_v[16777216];
__device__ float g_att[16777216];
__device__ float g_proj[16777216];

__device__ __forceinline__ float warpsum(float v) {
#pragma unroll
    for (int m = 16; m; m >>= 1) v += __shfl_xor_sync(0xffffffffu, v, m);
    return v;
}

// ---------------- K1: per-graph mean of each feature scale ----------------
// grid (B, L), 256 threads. Thread = (col-quad, row-group).
__global__ void segmean_kernel(const float* __restrict__ f0,
                               const float* __restrict__ f1,
                               const float* __restrict__ f2) {
    int b = blockIdx.x, l = blockIdx.y;
    const float* f = (l == 0) ? f0 : (l == 1 ? f1 : f2);
    int t = threadIdx.x;
    int cq = t & 63, rg = t >> 6;
    const float4* base = (const float4*)(f + (size_t)b * Sq * Dq);
    float4 acc = make_float4(0.f, 0.f, 0.f, 0.f);
#pragma unroll 4
    for (int s = rg; s < Sq; s += 4) {
        float4 v = base[s * 64 + cq];
        acc.x += v.x; acc.y += v.y; acc.z += v.z; acc.w += v.w;
    }
    __shared__ float4 red[4][64];
    red[rg][cq] = acc;
    __syncthreads();
    if (rg == 0) {
        float4 a = red[0][cq], b2 = red[1][cq], c = red[2][cq], d = red[3][cq];
        const float inv = 1.0f / (float)Sq;
        float4 o = make_float4((a.x + b2.x + c.x + d.x) * inv,
                               (a.y + b2.y + c.y + d.y) * inv,
                               (a.z + b2.z + c.z + d.z) * inv,
                               (a.w + b2.w + c.w + d.w) * inv);
        ((float4*)(g_mean + ((size_t)(b * Lq + l)) * Dq))[cq] = o;
    }
}

// ---------------- K2: scale attention -> scale_w [B,3] ----------------
// one CTA per graph, 256 threads
__global__ void scaleattn_kernel(const float* __restrict__ Wq_s, const float* __restrict__ bq_s,
                                 const float* __restrict__ Wk_s, const float* __restrict__ bk_s,
                                 const float* __restrict__ Wv_s, const float* __restrict__ bv_s) {
    int b = blockIdx.x;
    __shared__ float gm[Lq][Dq];
    __shared__ float qs[Lq][ADq], ks[Lq][ADq], vs[Lq][ADq];
    __shared__ float Am[Lq][Lq];
    __shared__ float ga[Lq][ADq];
    __shared__ float part[2][Lq];
    int t = threadIdx.x;
    int warp = t >> 5, lane = t & 31;
    for (int i = t; i < Lq * Dq; i += 256) gm[i / Dq][i % Dq] = g_mean[(size_t)b * Lq * Dq + i];
    __syncthreads();
    // 576 dot-products of length 256, one per warp-iteration (coalesced W reads)
    for (int o = warp; o < 3 * Lq * ADq; o += 8) {
        int mat = o / (Lq * ADq);
        int rem = o % (Lq * ADq);
        int l = rem >> 6, j = rem & 63;
        const float* W = (mat == 0) ? Wq_s : (mat == 1 ? Wk_s : Wv_s);
        const float* bb = (mat == 0) ? bq_s : (mat == 1 ? bk_s : bv_s);
        const float4* wr = (const float4*)(W + (size_t)j * Dq);
        const float4* gr = (const float4*)(&gm[l][0]);
        float4 w0 = wr[lane * 2], w1 = wr[lane * 2 + 1];
        float4 x0 = gr[lane * 2], x1 = gr[lane * 2 + 1];
        float p = w0.x * x0.x + w0.y * x0.y + w0.z * x0.z + w0.w * x0.w
                + w1.x * x1.x + w1.y * x1.y + w1.z * x1.z + w1.w * x1.w;
        p = warpsum(p);
        if (lane == 0) {
            float val = p + bb[j];
            if (mat == 0) qs[l][j] = val;
            else if (mat == 1) ks[l][j] = val;
            else vs[l][j] = val;
        }
    }
    __syncthreads();
    if (t < 9) {
        int li = t / 3, m = t % 3;
        float s = 0.f;
#pragma unroll
        for (int kk = 0; kk < ADq; kk++) s += qs[li][kk] * ks[m][kk];
        Am[li][m] = s * 0.125f;  // 1/sqrt(AD=64)
    }
    __syncthreads();
    if (t < 3) {
        float a0 = Am[t][0], a1 = Am[t][1], a2 = Am[t][2];
        float mx = fmaxf(a0, fmaxf(a1, a2));
        float e0 = __expf(a0 - mx), e1 = __expf(a1 - mx), e2 = __expf(a2 - mx);
        float inv = 1.f / (e0 + e1 + e2);
        Am[t][0] = e0 * inv; Am[t][1] = e1 * inv; Am[t][2] = e2 * inv;
    }
    __syncthreads();
    if (t < Lq * ADq) {
        int l = t >> 6, j = t & 63;
        ga[l][j] = Am[l][0] * vs[0][j] + Am[l][1] * vs[1][j] + Am[l][2] * vs[2][j];
    }
    __syncthreads();
    float w0 = 0.f, w1 = 0.f, w2 = 0.f;
    if (t < ADq) {  // warps 0 and 1, fully active
        float a0 = ga[0][t], a1 = ga[1][t], a2 = ga[2][t];
        float mx = fmaxf(a0, fmaxf(a1, a2));
        float e0 = __expf(a0 - mx), e1 = __expf(a1 - mx), e2 = __expf(a2 - mx);
        float inv = 1.f / (e0 + e1 + e2);
        w0 = warpsum(e0 * inv); w1 = warpsum(e1 * inv); w2 = warpsum(e2 * inv);
        if (lane == 0) { part[warp][0] = w0; part[warp][1] = w1; part[warp][2] = w2; }
    }
    __syncthreads();
    if (t < 3) g_scalew[b * Lq + t] = (part[0][t] + part[1][t]) * (1.0f / (float)ADq);
}

// ---------------- K3: fused = sum_l w[batch,l] * feat_l ----------------
__global__ void fuse_kernel(const float* __restrict__ f0, const float* __restrict__ f1,
                            const float* __restrict__ f2, const int* __restrict__ batch) {
    int idx = blockIdx.x * 256 + threadIdx.x;  // float4 index, total N*64
    int row = idx >> 6;
    int g = __ldg(&batch[row]);
    float w0 = g_scalew[g * 3 + 0], w1 = g_scalew[g * 3 + 1], w2 = g_scalew[g * 3 + 2];
    float4 a = ((const float4*)f0)[idx];
    float4 b = ((const float4*)f1)[idx];
    float4 c = ((const float4*)f2)[idx];
    float4 o = make_float4(w0 * a.x + w1 * b.x + w2 * c.x,
                           w0 * a.y + w1 * b.y + w2 * c.y,
                           w0 * a.z + w1 * b.z + w2 * c.z,
                           w0 * a.w + w1 * b.w + w2 * c.w);
    ((float4*)g_fused)[idx] = o;
}

// ---------------- K4: C = A[M,256] @ W[N,256]^T + bias ----------------
// BM=BN=64, BK=32, 256 threads, 4x4 register tile per thread.
// which: 0->g_fused->g_q  1->g_fused->g_k  2->g_fused->g_v  3->g_att->g_proj
__global__ void gemm_kernel(int which, const float* __restrict__ W, const float* __restrict__ bias) {
    const float* A = (which == 3) ? g_att : g_fused;
    float* C = (which == 0) ? g_q : (which == 1) ? g_k : (which == 2) ? g_v : g_proj;
    __shared__ float As[32][68];
    __shared__ float Bs[32][68];
    int t = threadIdx.x;
    int tx = t & 15, ty = t >> 4;
    int mBase = blockIdx.y * 64;
    int nBase = blockIdx.x * 64;
    const float* Ab = A + (size_t)mBase * Dq;
    const float* Wb = W + (size_t)nBase * Dq;
    float acc[4][4] = {};
    for (int kt = 0; kt < Dq; kt += 32) {
#pragma unroll
        for (int i = 0; i < 2; i++) {
            int fi = t + i * 256;
            int m = fi >> 3, kq = fi & 7;
            float4 v = *(const float4*)(Ab + (size_t)m * Dq + kt + kq * 4);
            As[kq * 4 + 0][m] = v.x; As[kq * 4 + 1][m] = v.y;
            As[kq * 4 + 2][m] = v.z; As[kq * 4 + 3][m] = v.w;
            float4 w = *(const float4*)(Wb + (size_t)m * Dq + kt + kq * 4);
            Bs[kq * 4 + 0][m] = w.x; Bs[kq * 4 + 1][m] = w.y;
            Bs[kq * 4 + 2][m] = w.z; Bs[kq * 4 + 3][m] = w.w;
        }
        __syncthreads();
#pragma unroll
        for (int k = 0; k < 32; k++) {
            float4 ra = *(const float4*)(&As[k][ty * 4]);
            float4 rb = *(const float4*)(&Bs[k][tx * 4]);
            acc[0][0] += ra.x * rb.x; acc[0][1] += ra.x * rb.y; acc[0][2] += ra.x * rb.z; acc[0][3] += ra.x * rb.w;
            acc[1][0] += ra.y * rb.x; acc[1][1] += ra.y * rb.y; acc[1][2] += ra.y * rb.z; acc[1][3] += ra.y * rb.w;
            acc[2][0] += ra.z * rb.x; acc[2][1] += ra.z * rb.y; acc[2][2] += ra.z * rb.z; acc[2][3] += ra.z * rb.w;
            acc[3][0] += ra.w * rb.x; acc[3][1] += ra.w * rb.y; acc[3][2] += ra.w * rb.z; acc[3][3] += ra.w * rb.w;
        }
        __syncthreads();
    }
    float4 bv = *(const float4*)(bias + nBase + tx * 4);
#pragma unroll
    for (int i = 0; i < 4; i++) {
        float4 o = make_float4(acc[i][0] + bv.x, acc[i][1] + bv.y, acc[i][2] + bv.z, acc[i][3] + bv.w);
        *(float4*)(C + (size_t)(mBase + ty * 4 + i) * Dq + nBase + tx * 4) = o;
    }
}

// ---------------- K5: flash attention, one CTA per (q-tile, b*h) ----------------
__global__ void attn_kernel() {
    __shared__ float Qs[32][68];   // [hd][qrow]
    __shared__ float Ks[32][68];   // [hd][krow]
    __shared__ float Vs[64][32];   // [krow][hd]
    __shared__ float Ps[64][68];   // [kcol][qrow]
    int t = threadIdx.x;
    int tx = t & 15, ty = t >> 4;
    int qt = blockIdx.x;
    int bh = blockIdx.y;
    int b = bh >> 3, h = bh & 7;
    const float* Qp = g_q + ((size_t)(b * Sq + qt * 64)) * Dq + h * HDq;
    const float* Kbase = g_k + ((size_t)b * Sq) * Dq + h * HDq;
    const float* Vbase = g_v + ((size_t)b * Sq) * Dq + h * HDq;
#pragma unroll
    for (int i = 0; i < 2; i++) {
        int fi = t + i * 256;
        int r = fi >> 3, hq = fi & 7;
        float4 v = *(const float4*)(Qp + (size_t)r * Dq + hq * 4);
        Qs[hq * 4 + 0][r] = v.x; Qs[hq * 4 + 1][r] = v.y;
        Qs[hq * 4 + 2][r] = v.z; Qs[hq * 4 + 3][r] = v.w;
    }
    float O[4][2] = {};
    float mrow[4] = {-1e30f, -1e30f, -1e30f, -1e30f};
    float lrow[4] = {};
    for (int ck = 0; ck < 8; ck++) {
        const float* Kp = Kbase + (size_t)(ck * 64) * Dq;
        const float* Vp = Vbase + (size_t)(ck * 64) * Dq;
        __syncthreads();  // protect Ks/Vs reuse (and Q store on first iter)
#pragma unroll
        for (int i = 0; i < 2; i++) {
            int fi = t + i * 256;
            int r = fi >> 3, hq = fi & 7;
            float4 v = *(const float4*)(Kp + (size_t)r * Dq + hq * 4);
            Ks[hq * 4 + 0][r] = v.x; Ks[hq * 4 + 1][r] = v.y;
            Ks[hq * 4 + 2][r] = v.z; Ks[hq * 4 + 3][r] = v.w;
            float4 w = *(const float4*)(Vp + (size_t)r * Dq + hq * 4);
            *(float4*)(&Vs[r][hq * 4]) = w;
        }
        __syncthreads();
        float s[4][4] = {};
#pragma unroll
        for (int k = 0; k < 32; k++) {
            float4 ra = *(const float4*)(&Qs[k][ty * 4]);
            float4 rb = *(const float4*)(&Ks[k][tx * 4]);
            s[0][0] += ra.x * rb.x; s[0][1] += ra.x * rb.y; s[0][2] += ra.x * rb.z; s[0][3] += ra.x * rb.w;
            s[1][0] += ra.y * rb.x; s[1][1] += ra.y * rb.y; s[1][2] += ra.y * rb.z; s[1][3] += ra.y * rb.w;
            s[2][0] += ra.z * rb.x; s[2][1] += ra.z * rb.y; s[2][2] += ra.z * rb.z; s[2][3] += ra.z * rb.w;
            s[3][0] += ra.w * rb.x; s[3][1] += ra.w * rb.y; s[3][2] += ra.w * rb.z; s[3][3] += ra.w * rb.w;
        }
        const float sc = 0.17677669529663687f;  // 1/sqrt(32)
#pragma unroll
        for (int i = 0; i < 4; i++) {
            float s0 = s[i][0] * sc, s1 = s[i][1] * sc, s2 = s[i][2] * sc, s3 = s[i][3] * sc;
            float rm = fmaxf(fmaxf(s0, s1), fmaxf(s2, s3));
#pragma unroll
            for (int m = 8; m; m >>= 1) rm = fmaxf(rm, __shfl_xor_sync(0xffffffffu, rm, m));
            float mn = fmaxf(mrow[i], rm);
            float p0 = __expf(s0 - mn), p1 = __expf(s1 - mn), p2 = __expf(s2 - mn), p3 = __expf(s3 - mn);
            float rs = p0 + p1 + p2 + p3;
#pragma unroll
            for (int m = 8; m; m >>= 1) rs += __shfl_xor_sync(0xffffffffu, rs, m);
            float alpha = __expf(mrow[i] - mn);
            lrow[i] = lrow[i] * alpha + rs;
            mrow[i] = mn;
            O[i][0] *= alpha; O[i][1] *= alpha;
            Ps[tx * 4 + 0][ty * 4 + i] = p0;
            Ps[tx * 4 + 1][ty * 4 + i] = p1;
            Ps[tx * 4 + 2][ty * 4 + i] = p2;
            Ps[tx * 4 + 3][ty * 4 + i] = p3;
        }
        __syncthreads();
#pragma unroll 8
        for (int c = 0; c < 64; c++) {
            float4 pv = *(const float4*)(&Ps[c][ty * 4]);
            float v0 = Vs[c][tx * 2], v1 = Vs[c][tx * 2 + 1];
            O[0][0] += pv.x * v0; O[0][1] += pv.x * v1;
            O[1][0] += pv.y * v0; O[1][1] += pv.y * v1;
            O[2][0] += pv.z * v0; O[2][1] += pv.z * v1;
            O[3][0] += pv.w * v0; O[3][1] += pv.w * v1;
        }
    }
    float* Op = g_att + ((size_t)(b * Sq + qt * 64)) * Dq + h * HDq;
#pragma unroll
    for (int i = 0; i < 4; i++) {
        float inv = 1.0f / lrow[i];
        Op[(size_t)(ty * 4 + i) * Dq + tx * 2 + 0] = O[i][0] * inv;
        Op[(size_t)(ty * 4 + i) * Dq + tx * 2 + 1] = O[i][1] * inv;
    }
}

// ---------------- K6: double layernorm epilogue ----------------
// out = LN2(fused + LN1(fused + proj)); one warp per row
__global__ void epilogue_kernel(const float* __restrict__ ln1g, const float* __restrict__ ln1b,
                                const float* __restrict__ ln2g, const float* __restrict__ ln2b,
                                float* __restrict__ out) {
    int row = blockIdx.x * 8 + (threadIdx.x >> 5);
    int lane = threadIdx.x & 31;
    const float4* f = (const float4*)(g_fused + (size_t)row * Dq);
    const float4* p = (const float4*)(g_proj + (size_t)row * Dq);
    float4 fa = f[lane], fb = f[lane + 32];
    float4 pa = p[lane], pb = p[lane + 32];
    float fv[8] = {fa.x, fa.y, fa.z, fa.w, fb.x, fb.y, fb.z, fb.w};
    float tt[8] = {fa.x + pa.x, fa.y + pa.y, fa.z + pa.z, fa.w + pa.w,
                   fb.x + pb.x, fb.y + pb.y, fb.z + pb.z, fb.w + pb.w};
    float s = 0.f;
#pragma unroll
    for (int k = 0; k < 8; k++) s += tt[k];
    float mean = warpsum(s) * (1.f / 256.f);
    float vsum = 0.f;
#pragma unroll
    for (int k = 0; k < 8; k++) { float d = tt[k] - mean; vsum += d * d; }
    float inv = rsqrtf(warpsum(vsum) * (1.f / 256.f) + 1e-5f);
    float4 g1a = ((const float4*)ln1g)[lane], g1b4 = ((const float4*)ln1g)[lane + 32];
    float4 b1a = ((const float4*)ln1b)[lane], b1b4 = ((const float4*)ln1b)[lane + 32];
    float g1[8] = {g1a.x, g1a.y, g1a.z, g1a.w, g1b4.x, g1b4.y, g1b4.z, g1b4.w};
    float b1[8] = {b1a.x, b1a.y, b1a.z, b1a.w, b1b4.x, b1b4.y, b1b4.z, b1b4.w};
    float u[8];
#pragma unroll
    for (int k = 0; k < 8; k++) u[k] = fv[k] + (tt[k] - mean) * inv * g1[k] + b1[k];
    float s2 = 0.f;
#pragma unroll
    for (int k = 0; k < 8; k++) s2 += u[k];
    float mean2 = warpsum(s2) * (1.f / 256.f);
    float vsum2 = 0.f;
#pragma unroll
    for (int k = 0; k < 8; k++) { float d = u[k] - mean2; vsum2 += d * d; }
    float inv2 = rsqrtf(warpsum(vsum2) * (1.f / 256.f) + 1e-5f);
    float4 g2a = ((const float4*)ln2g)[lane], g2b4 = ((const float4*)ln2g)[lane + 32];
    float4 b2a = ((const float4*)ln2b)[lane], b2b4 = ((const float4*)ln2b)[lane + 32];
    float g2[8] = {g2a.x, g2a.y, g2a.z, g2a.w, g2b4.x, g2b4.y, g2b4.z, g2b4.w};
    float b2[8] = {b2a.x, b2a.y, b2a.z, b2a.w, b2b4.x, b2b4.y, b2b4.z, b2b4.w};
    float r[8];
#pragma unroll
    for (int k = 0; k < 8; k++) r[k] = (u[k] - mean2) * inv2 * g2[k] + b2[k];
    float4* o = (float4*)(out + (size_t)row * Dq);
    o[lane] = make_float4(r[0], r[1], r[2], r[3]);
    o[lane + 32] = make_float4(r[4], r[5], r[6], r[7]);
}

// ---------------- launch ----------------
extern "C" void kernel_launch(void* const* d_in, const int* in_sizes, int n_in,
                              void* d_out, int out_size) {
    const float* f0 = (const float*)d_in[0];
    const float* f1 = (const float*)d_in[1];
    const float* f2 = (const float*)d_in[2];
    const int* batch = (const int*)d_in[3];
    const float* Wq_s = (const float*)d_in[4];  const float* bq_s = (const float*)d_in[5];
    const float* Wk_s = (const float*)d_in[6];  const float* bk_s = (const float*)d_in[7];
    const float* Wv_s = (const float*)d_in[8];  const float* bv_s = (const float*)d_in[9];
    const float* Wq = (const float*)d_in[10];   const float* bqv = (const float*)d_in[11];
    const float* Wk = (const float*)d_in[12];   const float* bkv = (const float*)d_in[13];
    const float* Wv = (const float*)d_in[14];   const float* bvv = (const float*)d_in[15];
    const float* Wo = (const float*)d_in[16];   const float* bov = (const float*)d_in[17];
    const float* l1g = (const float*)d_in[18];  const float* l1b = (const float*)d_in[19];
    const float* l2g = (const float*)d_in[20];  const float* l2b = (const float*)d_in[21];
    float* out = (float*)d_out;

    segmean_kernel<<<dim3(Bq, Lq), 256>>>(f0, f1, f2);
    scaleattn_kernel<<<Bq, 256>>>(Wq_s, bq_s, Wk_s, bk_s, Wv_s, bv_s);
    fuse_kernel<<<(Nq * (Dq / 4)) / 256, 256>>>(f0, f1, f2, batch);
    gemm_kernel<<<dim3(Dq / 64, Nq / 64), 256>>>(0, Wq, bqv);
    gemm_kernel<<<dim3(Dq / 64, Nq / 64), 256>>>(1, Wk, bkv);
    gemm_kernel<<<dim3(Dq / 64, Nq / 64), 256>>>(2, Wv, bvv);
    attn_kernel<<<dim3(Sq / 64, Bq * Hq), 256>>>();
    gemm_kernel<<<dim3(Dq / 64, Nq / 64), 256>>>(3, Wo, bov);
    epilogue_kernel<<<Nq / 8, 256>>>(l1g, l1b, l2g, l2b, out);
}

// round 8
// speedup vs baseline: 1.0006x; 1.0006x over previous
#include <cuda_runtime.h>

#define Bq 128
#define Sq 512
#define Dq 256
#define Lq 3
#define Hq 8
#define ADq 64
#define HDq 32
#define Nq (Bq*Sq)   // 65536

// ---------------- scratch (device globals; no allocation) ----------------
__device__ float g_mean[Bq*Lq*Dq];
__device__ float g_scalew[Bq*Lq];
__device__ float g_fused[16777216];  // N*D
__device__ float g_q[16777216];
__device__ float g_k[16777216];
__device__ float g_v[16777216];
__device__ float g_att[16777216];
__device__ float g_proj[16777216];

__device__ __forceinline__ float warpsum(float v) {
#pragma unroll
    for (int m = 16; m; m >>= 1) v += __shfl_xor_sync(0xffffffffu, v, m);
    return v;
}

// ---------------- K1: per-graph mean of each feature scale ----------------
// grid (B, L), 256 threads. Thread = (col-quad, row-group).
__global__ void segmean_kernel(const float* __restrict__ f0,
                               const float* __restrict__ f1,
                               const float* __restrict__ f2) {
    int b = blockIdx.x, l = blockIdx.y;
    const float* f = (l == 0) ? f0 : (l == 1 ? f1 : f2);
    int t = threadIdx.x;
    int cq = t & 63, rg = t >> 6;
    const float4* base = (const float4*)(f + (size_t)b * Sq * Dq);
    float4 acc = make_float4(0.f, 0.f, 0.f, 0.f);
#pragma unroll 4
    for (int s = rg; s < Sq; s += 4) {
        float4 v = base[s * 64 + cq];
        acc.x += v.x; acc.y += v.y; acc.z += v.z; acc.w += v.w;
    }
    __shared__ float4 red[4][64];
    red[rg][cq] = acc;
    __syncthreads();
    if (rg == 0) {
        float4 a = red[0][cq], b2 = red[1][cq], c = red[2][cq], d = red[3][cq];
        const float inv = 1.0f / (float)Sq;
        float4 o = make_float4((a.x + b2.x + c.x + d.x) * inv,
                               (a.y + b2.y + c.y + d.y) * inv,
                               (a.z + b2.z + c.z + d.z) * inv,
                               (a.w + b2.w + c.w + d.w) * inv);
        ((float4*)(g_mean + ((size_t)(b * Lq + l)) * Dq))[cq] = o;
    }
}

// ---------------- K2: scale attention -> scale_w [B,3] ----------------
// one CTA per graph, 256 threads
__global__ void scaleattn_kernel(const float* __restrict__ Wq_s, const float* __restrict__ bq_s,
                                 const float* __restrict__ Wk_s, const float* __restrict__ bk_s,
                                 const float* __restrict__ Wv_s, const float* __restrict__ bv_s) {
    int b = blockIdx.x;
    __shared__ float gm[Lq][Dq];
    __shared__ float qs[Lq][ADq], ks[Lq][ADq], vs[Lq][ADq];
    __shared__ float Am[Lq][Lq];
    __shared__ float ga[Lq][ADq];
    __shared__ float part[2][Lq];
    int t = threadIdx.x;
    int warp = t >> 5, lane = t & 31;
    for (int i = t; i < Lq * Dq; i += 256) gm[i / Dq][i % Dq] = g_mean[(size_t)b * Lq * Dq + i];
    __syncthreads();
    // 576 dot-products of length 256, one per warp-iteration (coalesced W reads)
    for (int o = warp; o < 3 * Lq * ADq; o += 8) {
        int mat = o / (Lq * ADq);
        int rem = o % (Lq * ADq);
        int l = rem >> 6, j = rem & 63;
        const float* W = (mat == 0) ? Wq_s : (mat == 1 ? Wk_s : Wv_s);
        const float* bb = (mat == 0) ? bq_s : (mat == 1 ? bk_s : bv_s);
        const float4* wr = (const float4*)(W + (size_t)j * Dq);
        const float4* gr = (const float4*)(&gm[l][0]);
        float4 w0 = wr[lane * 2], w1 = wr[lane * 2 + 1];
        float4 x0 = gr[lane * 2], x1 = gr[lane * 2 + 1];
        float p = w0.x * x0.x + w0.y * x0.y + w0.z * x0.z + w0.w * x0.w
                + w1.x * x1.x + w1.y * x1.y + w1.z * x1.z + w1.w * x1.w;
        p = warpsum(p);
        if (lane == 0) {
            float val = p + bb[j];
            if (mat == 0) qs[l][j] = val;
            else if (mat == 1) ks[l][j] = val;
            else vs[l][j] = val;
        }
    }
    __syncthreads();
    if (t < 9) {
        int li = t / 3, m = t % 3;
        float s = 0.f;
#pragma unroll
        for (int kk = 0; kk < ADq; kk++) s += qs[li][kk] * ks[m][kk];
        Am[li][m] = s * 0.125f;  // 1/sqrt(AD=64)
    }
    __syncthreads();
    if (t < 3) {
        float a0 = Am[t][0], a1 = Am[t][1], a2 = Am[t][2];
        float mx = fmaxf(a0, fmaxf(a1, a2));
        float e0 = __expf(a0 - mx), e1 = __expf(a1 - mx), e2 = __expf(a2 - mx);
        float inv = 1.f / (e0 + e1 + e2);
        Am[t][0] = e0 * inv; Am[t][1] = e1 * inv; Am[t][2] = e2 * inv;
    }
    __syncthreads();
    if (t < Lq * ADq) {
        int l = t >> 6, j = t & 63;
        ga[l][j] = Am[l][0] * vs[0][j] + Am[l][1] * vs[1][j] + Am[l][2] * vs[2][j];
    }
    __syncthreads();
    float w0 = 0.f, w1 = 0.f, w2 = 0.f;
    if (t < ADq) {  // warps 0 and 1, fully active
        float a0 = ga[0][t], a1 = ga[1][t], a2 = ga[2][t];
        float mx = fmaxf(a0, fmaxf(a1, a2));
        float e0 = __expf(a0 - mx), e1 = __expf(a1 - mx), e2 = __expf(a2 - mx);
        float inv = 1.f / (e0 + e1 + e2);
        w0 = warpsum(e0 * inv); w1 = warpsum(e1 * inv); w2 = warpsum(e2 * inv);
        if (lane == 0) { part[warp][0] = w0; part[warp][1] = w1; part[warp][2] = w2; }
    }
    __syncthreads();
    if (t < 3) g_scalew[b * Lq + t] = (part[0][t] + part[1][t]) * (1.0f / (float)ADq);
}

// ---------------- K3: fused = sum_l w[batch,l] * feat_l ----------------
__global__ void fuse_kernel(const float* __restrict__ f0, const float* __restrict__ f1,
                            const float* __restrict__ f2, const int* __restrict__ batch) {
    int idx = blockIdx.x * 256 + threadIdx.x;  // float4 index, total N*64
    int row = idx >> 6;
    int g = __ldg(&batch[row]);
    float w0 = g_scalew[g * 3 + 0], w1 = g_scalew[g * 3 + 1], w2 = g_scalew[g * 3 + 2];
    float4 a = ((const float4*)f0)[idx];
    float4 b = ((const float4*)f1)[idx];
    float4 c = ((const float4*)f2)[idx];
    float4 o = make_float4(w0 * a.x + w1 * b.x + w2 * c.x,
                           w0 * a.y + w1 * b.y + w2 * c.y,
                           w0 * a.z + w1 * b.z + w2 * c.z,
                           w0 * a.w + w1 * b.w + w2 * c.w);
    ((float4*)g_fused)[idx] = o;
}

// ---------------- K4: C = A[M,256] @ W[N,256]^T + bias ----------------
// BM=BN=64, BK=32, 256 threads, 4x4 register tile per thread.
// which: 0->g_fused->g_q  1->g_fused->g_k  2->g_fused->g_v  3->g_att->g_proj
__global__ void gemm_kernel(int which, const float* __restrict__ W, const float* __restrict__ bias) {
    const float* A = (which == 3) ? g_att : g_fused;
    float* C = (which == 0) ? g_q : (which == 1) ? g_k : (which == 2) ? g_v : g_proj;
    __shared__ float As[32][68];
    __shared__ float Bs[32][68];
    int t = threadIdx.x;
    int tx = t & 15, ty = t >> 4;
    int mBase = blockIdx.y * 64;
    int nBase = blockIdx.x * 64;
    const float* Ab = A + (size_t)mBase * Dq;
    const float* Wb = W + (size_t)nBase * Dq;
    float acc[4][4] = {};
    for (int kt = 0; kt < Dq; kt += 32) {
#pragma unroll
        for (int i = 0; i < 2; i++) {
            int fi = t + i * 256;
            int m = fi >> 3, kq = fi & 7;
            float4 v = *(const float4*)(Ab + (size_t)m * Dq + kt + kq * 4);
            As[kq * 4 + 0][m] = v.x; As[kq * 4 + 1][m] = v.y;
            As[kq * 4 + 2][m] = v.z; As[kq * 4 + 3][m] = v.w;
            float4 w = *(const float4*)(Wb + (size_t)m * Dq + kt + kq * 4);
            Bs[kq * 4 + 0][m] = w.x; Bs[kq * 4 + 1][m] = w.y;
            Bs[kq * 4 + 2][m] = w.z; Bs[kq * 4 + 3][m] = w.w;
        }
        __syncthreads();
#pragma unroll
        for (int k = 0; k < 32; k++) {
            float4 ra = *(const float4*)(&As[k][ty * 4]);
            float4 rb = *(const float4*)(&Bs[k][tx * 4]);
            acc[0][0] += ra.x * rb.x; acc[0][1] += ra.x * rb.y; acc[0][2] += ra.x * rb.z; acc[0][3] += ra.x * rb.w;
            acc[1][0] += ra.y * rb.x; acc[1][1] += ra.y * rb.y; acc[1][2] += ra.y * rb.z; acc[1][3] += ra.y * rb.w;
            acc[2][0] += ra.z * rb.x; acc[2][1] += ra.z * rb.y; acc[2][2] += ra.z * rb.z; acc[2][3] += ra.z * rb.w;
            acc[3][0] += ra.w * rb.x; acc[3][1] += ra.w * rb.y; acc[3][2] += ra.w * rb.z; acc[3][3] += ra.w * rb.w;
        }
        __syncthreads();
    }
    float4 bv = *(const float4*)(bias + nBase + tx * 4);
#pragma unroll
    for (int i = 0; i < 4; i++) {
        float4 o = make_float4(acc[i][0] + bv.x, acc[i][1] + bv.y, acc[i][2] + bv.z, acc[i][3] + bv.w);
        *(float4*)(C + (size_t)(mBase + ty * 4 + i) * Dq + nBase + tx * 4) = o;
    }
}

// ---------------- K5: flash attention, one CTA per (q-tile, b*h) ----------------
__global__ void attn_kernel() {
    __shared__ float Qs[32][68];   // [hd][qrow]
    __shared__ float Ks[32][68];   // [hd][krow]
    __shared__ float Vs[64][32];   // [krow][hd]
    __shared__ float Ps[64][68];   // [kcol][qrow]
    int t = threadIdx.x;
    int tx = t & 15, ty = t >> 4;
    int qt = blockIdx.x;
    int bh = blockIdx.y;
    int b = bh >> 3, h = bh & 7;
    const float* Qp = g_q + ((size_t)(b * Sq + qt * 64)) * Dq + h * HDq;
    const float* Kbase = g_k + ((size_t)b * Sq) * Dq + h * HDq;
    const float* Vbase = g_v + ((size_t)b * Sq) * Dq + h * HDq;
#pragma unroll
    for (int i = 0; i < 2; i++) {
        int fi = t + i * 256;
        int r = fi >> 3, hq = fi & 7;
        float4 v = *(const float4*)(Qp + (size_t)r * Dq + hq * 4);
        Qs[hq * 4 + 0][r] = v.x; Qs[hq * 4 + 1][r] = v.y;
        Qs[hq * 4 + 2][r] = v.z; Qs[hq * 4 + 3][r] = v.w;
    }
    float O[4][2] = {};
    float mrow[4] = {-1e30f, -1e30f, -1e30f, -1e30f};
    float lrow[4] = {};
    for (int ck = 0; ck < 8; ck++) {
        const float* Kp = Kbase + (size_t)(ck * 64) * Dq;
        const float* Vp = Vbase + (size_t)(ck * 64) * Dq;
        __syncthreads();  // protect Ks/Vs reuse (and Q store on first iter)
#pragma unroll
        for (int i = 0; i < 2; i++) {
            int fi = t + i * 256;
            int r = fi >> 3, hq = fi & 7;
            float4 v = *(const float4*)(Kp + (size_t)r * Dq + hq * 4);
            Ks[hq * 4 + 0][r] = v.x; Ks[hq * 4 + 1][r] = v.y;
            Ks[hq * 4 + 2][r] = v.z; Ks[hq * 4 + 3][r] = v.w;
            float4 w = *(const float4*)(Vp + (size_t)r * Dq + hq * 4);
            *(float4*)(&Vs[r][hq * 4]) = w;
        }
        __syncthreads();
        float s[4][4] = {};
#pragma unroll
        for (int k = 0; k < 32; k++) {
            float4 ra = *(const float4*)(&Qs[k][ty * 4]);
            float4 rb = *(const float4*)(&Ks[k][tx * 4]);
            s[0][0] += ra.x * rb.x; s[0][1] += ra.x * rb.y; s[0][2] += ra.x * rb.z; s[0][3] += ra.x * rb.w;
            s[1][0] += ra.y * rb.x; s[1][1] += ra.y * rb.y; s[1][2] += ra.y * rb.z; s[1][3] += ra.y * rb.w;
            s[2][0] += ra.z * rb.x; s[2][1] += ra.z * rb.y; s[2][2] += ra.z * rb.z; s[2][3] += ra.z * rb.w;
            s[3][0] += ra.w * rb.x; s[3][1] += ra.w * rb.y; s[3][2] += ra.w * rb.z; s[3][3] += ra.w * rb.w;
        }
        const float sc = 0.17677669529663687f;  // 1/sqrt(32)
#pragma unroll
        for (int i = 0; i < 4; i++) {
            float s0 = s[i][0] * sc, s1 = s[i][1] * sc, s2 = s[i][2] * sc, s3 = s[i][3] * sc;
            float rm = fmaxf(fmaxf(s0, s1), fmaxf(s2, s3));
#pragma unroll
            for (int m = 8; m; m >>= 1) rm = fmaxf(rm, __shfl_xor_sync(0xffffffffu, rm, m));
            float mn = fmaxf(mrow[i], rm);
            float p0 = __expf(s0 - mn), p1 = __expf(s1 - mn), p2 = __expf(s2 - mn), p3 = __expf(s3 - mn);
            float rs = p0 + p1 + p2 + p3;
#pragma unroll
            for (int m = 8; m; m >>= 1) rs += __shfl_xor_sync(0xffffffffu, rs, m);
            float alpha = __expf(mrow[i] - mn);
            lrow[i] = lrow[i] * alpha + rs;
            mrow[i] = mn;
            O[i][0] *= alpha; O[i][1] *= alpha;
            Ps[tx * 4 + 0][ty * 4 + i] = p0;
            Ps[tx * 4 + 1][ty * 4 + i] = p1;
            Ps[tx * 4 + 2][ty * 4 + i] = p2;
            Ps[tx * 4 + 3][ty * 4 + i] = p3;
        }
        __syncthreads();
#pragma unroll 8
        for (int c = 0; c < 64; c++) {
            float4 pv = *(const float4*)(&Ps[c][ty * 4]);
            float v0 = Vs[c][tx * 2], v1 = Vs[c][tx * 2 + 1];
            O[0][0] += pv.x * v0; O[0][1] += pv.x * v1;
            O[1][0] += pv.y * v0; O[1][1] += pv.y * v1;
            O[2][0] += pv.z * v0; O[2][1] += pv.z * v1;
            O[3][0] += pv.w * v0; O[3][1] += pv.w * v1;
        }
    }
    float* Op = g_att + ((size_t)(b * Sq + qt * 64)) * Dq + h * HDq;
#pragma unroll
    for (int i = 0; i < 4; i++) {
        float inv = 1.0f / lrow[i];
        Op[(size_t)(ty * 4 + i) * Dq + tx * 2 + 0] = O[i][0] * inv;
        Op[(size_t)(ty * 4 + i) * Dq + tx * 2 + 1] = O[i][1] * inv;
    }
}

// ---------------- K6: double layernorm epilogue ----------------
// out = LN2(fused + LN1(fused + proj)); one warp per row
__global__ void epilogue_kernel(const float* __restrict__ ln1g, const float* __restrict__ ln1b,
                                const float* __restrict__ ln2g, const float* __restrict__ ln2b,
                                float* __restrict__ out) {
    int row = blockIdx.x * 8 + (threadIdx.x >> 5);
    int lane = threadIdx.x & 31;
    const float4* f = (const float4*)(g_fused + (size_t)row * Dq);
    const float4* p = (const float4*)(g_proj + (size_t)row * Dq);
    float4 fa = f[lane], fb = f[lane + 32];
    float4 pa = p[lane], pb = p[lane + 32];
    float fv[8] = {fa.x, fa.y, fa.z, fa.w, fb.x, fb.y, fb.z, fb.w};
    float tt[8] = {fa.x + pa.x, fa.y + pa.y, fa.z + pa.z, fa.w + pa.w,
                   fb.x + pb.x, fb.y + pb.y, fb.z + pb.z, fb.w + pb.w};
    float s = 0.f;
#pragma unroll
    for (int k = 0; k < 8; k++) s += tt[k];
    float mean = warpsum(s) * (1.f / 256.f);
    float vsum = 0.f;
#pragma unroll
    for (int k = 0; k < 8; k++) { float d = tt[k] - mean; vsum += d * d; }
    float inv = rsqrtf(warpsum(vsum) * (1.f / 256.f) + 1e-5f);
    float4 g1a = ((const float4*)ln1g)[lane], g1b4 = ((const float4*)ln1g)[lane + 32];
    float4 b1a = ((const float4*)ln1b)[lane], b1b4 = ((const float4*)ln1b)[lane + 32];
    float g1[8] = {g1a.x, g1a.y, g1a.z, g1a.w, g1b4.x, g1b4.y, g1b4.z, g1b4.w};
    float b1[8] = {b1a.x, b1a.y, b1a.z, b1a.w, b1b4.x, b1b4.y, b1b4.z, b1b4.w};
    float u[8];
#pragma unroll
    for (int k = 0; k < 8; k++) u[k] = fv[k] + (tt[k] - mean) * inv * g1[k] + b1[k];
    float s2 = 0.f;
#pragma unroll
    for (int k = 0; k < 8; k++) s2 += u[k];
    float mean2 = warpsum(s2) * (1.f / 256.f);
    float vsum2 = 0.f;
#pragma unroll
    for (int k = 0; k < 8; k++) { float d = u[k] - mean2; vsum2 += d * d; }
    float inv2 = rsqrtf(warpsum(vsum2) * (1.f / 256.f) + 1e-5f);
    float4 g2a = ((const float4*)ln2g)[lane], g2b4 = ((const float4*)ln2g)[lane + 32];
    float4 b2a = ((const float4*)ln2b)[lane], b2b4 = ((const float4*)ln2b)[lane + 32];
    float g2[8] = {g2a.x, g2a.y, g2a.z, g2a.w, g2b4.x, g2b4.y, g2b4.z, g2b4.w};
    float b2[8] = {b2a.x, b2a.y, b2a.z, b2a.w, b2b4.x, b2b4.y, b2b4.z, b2b4.w};
    float r[8];
#pragma unroll
    for (int k = 0; k < 8; k++) r[k] = (u[k] - mean2) * inv2 * g2[k] + b2[k];
    float4* o = (float4*)(out + (size_t)row * Dq);
    o[lane] = make_float4(r[0], r[1], r[2], r[3]);
    o[lane + 32] = make_float4(r[4], r[5], r[6], r[7]);
}

// ---------------- launch ----------------
extern "C" void kernel_launch(void* const* d_in, const int* in_sizes, int n_in,
                              void* d_out, int out_size) {
    const float* f0 = (const float*)d_in[0];
    const float* f1 = (const float*)d_in[1];
    const float* f2 = (const float*)d_in[2];
    const int* batch = (const int*)d_in[3];
    const float* Wq_s = (const float*)d_in[4];  const float* bq_s = (const float*)d_in[5];
    const float* Wk_s = (const float*)d_in[6];  const float* bk_s = (const float*)d_in[7];
    const float* Wv_s = (const float*)d_in[8];  const float* bv_s = (const float*)d_in[9];
    const float* Wq = (const float*)d_in[10];   const float* bqv = (const float*)d_in[11];
    const float* Wk = (const float*)d_in[12];   const float* bkv = (const float*)d_in[13];
    const float* Wv = (const float*)d_in[14];   const float* bvv = (const float*)d_in[15];
    const float* Wo = (const float*)d_in[16];   const float* bov = (const float*)d_in[17];
    const float* l1g = (const float*)d_in[18];  const float* l1b = (const float*)d_in[19];
    const float* l2g = (const float*)d_in[20];  const float* l2b = (const float*)d_in[21];
    float* out = (float*)d_out;

    segmean_kernel<<<dim3(Bq, Lq), 256>>>(f0, f1, f2);
    scaleattn_kernel<<<Bq, 256>>>(Wq_s, bq_s, Wk_s, bk_s, Wv_s, bv_s);
    fuse_kernel<<<(Nq * (Dq / 4)) / 256, 256>>>(f0, f1, f2, batch);
    gemm_kernel<<<dim3(Dq / 64, Nq / 64), 256>>>(0, Wq, bqv);
    gemm_kernel<<<dim3(Dq / 64, Nq / 64), 256>>>(1, Wk, bkv);
    gemm_kernel<<<dim3(Dq / 64, Nq / 64), 256>>>(2, Wv, bvv);
    attn_kernel<<<dim3(Sq / 64, Bq * Hq), 256>>>();
    gemm_kernel<<<dim3(Dq / 64, Nq / 64), 256>>>(3, Wo, bov);
    epilogue_kernel<<<Nq / 8, 256>>>(l1g, l1b, l2g, l2b, out);
}